// round 3
// baseline (speedup 1.0000x reference)
#include <cuda_runtime.h>
#include <math.h>

// Mamba dims
#define LL   1024
#define DD   1024
#define DIN  2048
#define NS   16
#define RR   64
#define BL   2048      // B*L
#define XZW  4096      // 2*DIN

// ---------------- scratch (device globals; no allocation allowed) ----------
__device__ float g_xz[BL * XZW];      // in_proj output [2048, 4096]
__device__ float g_xconv[BL * DIN];   // conv+silu     [2048, 2048]
__device__ float g_xdbl[BL * 96];     // x_proj        [2048, 96]
__device__ float g_delta[BL * DIN];   // softplus(dt@W_dt+b) [2048, 2048]
__device__ float g_yg[BL * DIN];      // gated scan out [2048, 2048]
__device__ float g_outp[BL * DD];     // pre-LN output  [2048, 1024]

// ---------------- SGEMM: C[M,N] = A[M,K] @ B[K,N], all row-major ----------
__global__ __launch_bounds__(256) void sgemm128(
    const float* __restrict__ A, const float* __restrict__ Bm,
    float* __restrict__ C, int M, int N, int Kd)
{
    const int BK = 8;
    __shared__ float As[BK][128];
    __shared__ float Bs[BK][128];

    int tid = threadIdx.x;
    A  += (size_t)blockIdx.y * 128 * Kd;
    Bm += (size_t)blockIdx.x * 128;
    C  += (size_t)blockIdx.y * 128 * N + blockIdx.x * 128;

    int arow = tid >> 1, acol = (tid & 1) << 2;       // A: 128x8 tile, float4 each
    int brl  = tid >> 5, bcl  = (tid & 31) << 2;      // B: 8x128 tile
    int trow = (tid >> 4) << 3, tcol = (tid & 15) << 3;

    float acc[8][8];
    #pragma unroll
    for (int i = 0; i < 8; i++)
        #pragma unroll
        for (int j = 0; j < 8; j++) acc[i][j] = 0.f;

    for (int k0 = 0; k0 < Kd; k0 += BK) {
        float4 av = *(const float4*)(A + (size_t)arow * Kd + k0 + acol);
        As[acol + 0][arow] = av.x;
        As[acol + 1][arow] = av.y;
        As[acol + 2][arow] = av.z;
        As[acol + 3][arow] = av.w;
        float4 bv = *(const float4*)(Bm + (size_t)(k0 + brl) * N + bcl);
        *(float4*)(&Bs[brl][bcl]) = bv;
        __syncthreads();

        #pragma unroll
        for (int k = 0; k < BK; k++) {
            float ra[8], rb[8];
            #pragma unroll
            for (int i = 0; i < 8; i++) ra[i] = As[k][trow + i];
            #pragma unroll
            for (int j = 0; j < 8; j++) rb[j] = Bs[k][tcol + j];
            #pragma unroll
            for (int i = 0; i < 8; i++)
                #pragma unroll
                for (int j = 0; j < 8; j++)
                    acc[i][j] = fmaf(ra[i], rb[j], acc[i][j]);
        }
        __syncthreads();
    }

    #pragma unroll
    for (int i = 0; i < 8; i++) {
        float4 v0 = make_float4(acc[i][0], acc[i][1], acc[i][2], acc[i][3]);
        float4 v1 = make_float4(acc[i][4], acc[i][5], acc[i][6], acc[i][7]);
        *(float4*)(C + (size_t)(trow + i) * N + tcol)     = v0;
        *(float4*)(C + (size_t)(trow + i) * N + tcol + 4) = v1;
    }
}

// ---------------- causal depthwise conv (K=4) + SiLU ----------------------
__global__ void conv_silu_kernel(const float* __restrict__ conv_w,
                                 const float* __restrict__ conv_b)
{
    int idx = blockIdx.x * blockDim.x + threadIdx.x;   // over BL*DIN
    int d   = idx & (DIN - 1);
    int row = idx >> 11;
    int l   = row & (LL - 1);
    float acc = conv_b[d];
    #pragma unroll
    for (int k = 0; k < 4; k++) {
        int ll = l + k - 3;
        if (ll >= 0)
            acc = fmaf(g_xz[(size_t)(row + k - 3) * XZW + d], conv_w[d * 4 + k], acc);
    }
    acc = acc / (1.f + __expf(-acc));     // silu
    g_xconv[idx] = acc;
}

// ---------------- x_dbl = x_conv @ W_x  ([2048,2048]@[2048,96]) -----------
// block: (96, 8) threads; 8 rows per block; per-thread full-K dot.
__global__ void xdbl_kernel(const float* __restrict__ W_x)
{
    int c   = threadIdx.x;              // 0..95
    int row = blockIdx.x * 8 + threadIdx.y;
    const float* xrow = g_xconv + (size_t)row * DIN;
    float acc = 0.f;
    #pragma unroll 4
    for (int k = 0; k < DIN; k++)
        acc = fmaf(__ldg(xrow + k), __ldg(W_x + k * 96 + c), acc);
    g_xdbl[(size_t)row * 96 + c] = acc;
}

// ---------------- delta = softplus(dt @ W_dt + b_dt) ----------------------
// 8 rows/block, 256 threads stride over DIN cols.
__global__ void delta_kernel(const float* __restrict__ W_dt,
                             const float* __restrict__ b_dt)
{
    __shared__ float sdt[8][RR];
    int tid  = threadIdx.x;
    int row0 = blockIdx.x * 8;
    for (int i = tid; i < 8 * RR; i += 256)
        sdt[i / RR][i % RR] = g_xdbl[(size_t)(row0 + i / RR) * 96 + (i % RR)];
    __syncthreads();

    for (int d = tid; d < DIN; d += 256) {
        float bias = b_dt[d];
        float acc[8];
        #pragma unroll
        for (int j = 0; j < 8; j++) acc[j] = bias;
        #pragma unroll
        for (int r = 0; r < RR; r++) {
            float w = W_dt[r * DIN + d];
            #pragma unroll
            for (int j = 0; j < 8; j++) acc[j] = fmaf(sdt[j][r], w, acc[j]);
        }
        #pragma unroll
        for (int j = 0; j < 8; j++) {
            float v = acc[j];
            float sp = (v > 20.f) ? v : log1pf(__expf(v));
            g_delta[(size_t)(row0 + j) * DIN + d] = sp;
        }
    }
}

// ---------------- selective scan + D-skip + z-gate ------------------------
// 16 lanes per (b,d) channel (one lane per state n); 2 channels/warp.
__global__ void scan_kernel(const float* __restrict__ A_log,
                            const float* __restrict__ D_skip)
{
    int lane = threadIdx.x & 31;
    int grp  = lane >> 4;          // 0/1: which channel in this warp
    int n    = lane & 15;
    int wglobal = blockIdx.x * (blockDim.x >> 5) + (threadIdx.x >> 5);
    int ch = wglobal * 2 + grp;    // 0..4095
    int b  = ch >> 11;
    int d  = ch & (DIN - 1);

    float a  = -__expf(A_log[d * NS + n]);
    float Dv = D_skip[d];

    const float* deltaP = g_delta + (size_t)(b * LL) * DIN + d;
    const float* xcP    = g_xconv + (size_t)(b * LL) * DIN + d;
    const float* zP     = g_xz    + (size_t)(b * LL) * XZW + DIN + d;
    const float* bcP    = g_xdbl  + (size_t)(b * LL) * 96 + RR + n;
    float*       ygP    = g_yg    + (size_t)(b * LL) * DIN + d;

    float h = 0.f;
    #pragma unroll 4
    for (int l = 0; l < LL; l++) {
        float dv = __ldg(deltaP + (size_t)l * DIN);
        float xv = __ldg(xcP + (size_t)l * DIN);
        float Bv = __ldg(bcP + (size_t)l * 96);
        float Cv = __ldg(bcP + (size_t)l * 96 + NS);
        float dA = __expf(dv * a);
        h = fmaf(dA, h, dv * Bv * xv);
        float yc = h * Cv;
        yc += __shfl_xor_sync(0xFFFFFFFFu, yc, 8);
        yc += __shfl_xor_sync(0xFFFFFFFFu, yc, 4);
        yc += __shfl_xor_sync(0xFFFFFFFFu, yc, 2);
        yc += __shfl_xor_sync(0xFFFFFFFFu, yc, 1);
        if (n == 0) {
            float zv = zP[(size_t)l * XZW];
            float gate = zv / (1.f + __expf(-zv));
            ygP[(size_t)l * DIN] = (yc + xv * Dv) * gate;
        }
    }
}

// ---------------- LayerNorm (row = 1024) ----------------------------------
__global__ void ln_kernel(const float* __restrict__ lng,
                          const float* __restrict__ lnb,
                          float* __restrict__ out)
{
    int row = blockIdx.x, tid = threadIdx.x;
    float4 v = ((const float4*)(g_outp + (size_t)row * DD))[tid];
    float s  = v.x + v.y + v.z + v.w;
    float sq = fmaf(v.x, v.x, fmaf(v.y, v.y, fmaf(v.z, v.z, v.w * v.w)));
    #pragma unroll
    for (int o = 16; o > 0; o >>= 1) {
        s  += __shfl_xor_sync(0xFFFFFFFFu, s, o);
        sq += __shfl_xor_sync(0xFFFFFFFFu, sq, o);
    }
    __shared__ float ss[8], ssq[8];
    int w = tid >> 5, lane = tid & 31;
    if (!lane) { ss[w] = s; ssq[w] = sq; }
    __syncthreads();
    if (tid < 32) {
        s  = (lane < 8) ? ss[lane]  : 0.f;
        sq = (lane < 8) ? ssq[lane] : 0.f;
        #pragma unroll
        for (int o = 4; o > 0; o >>= 1) {
            s  += __shfl_xor_sync(0xFFFFFFFFu, s, o);
            sq += __shfl_xor_sync(0xFFFFFFFFu, sq, o);
        }
        if (!lane) { ss[0] = s; ssq[0] = sq; }
    }
    __syncthreads();
    float mu  = ss[0] * (1.f / 1024.f);
    float var = ssq[0] * (1.f / 1024.f) - mu * mu;
    float inv = rsqrtf(var + 1e-5f);
    float4 g4 = ((const float4*)lng)[tid];
    float4 b4 = ((const float4*)lnb)[tid];
    float4 o4;
    o4.x = (v.x - mu) * inv * g4.x + b4.x;
    o4.y = (v.y - mu) * inv * g4.y + b4.y;
    o4.z = (v.z - mu) * inv * g4.z + b4.z;
    o4.w = (v.w - mu) * inv * g4.w + b4.w;
    ((float4*)(out + (size_t)row * DD))[tid] = o4;
}

// ---------------- launcher -------------------------------------------------
extern "C" void kernel_launch(void* const* d_in, const int* in_sizes, int n_in,
                              void* d_out, int out_size)
{
    const float* x      = (const float*)d_in[0];
    const float* W_in   = (const float*)d_in[1];
    const float* conv_w = (const float*)d_in[2];
    const float* conv_b = (const float*)d_in[3];
    const float* W_x    = (const float*)d_in[4];
    const float* W_dt   = (const float*)d_in[5];
    const float* b_dt   = (const float*)d_in[6];
    const float* A_log  = (const float*)d_in[7];
    const float* D_skip = (const float*)d_in[8];
    const float* W_out  = (const float*)d_in[9];
    const float* ln_g   = (const float*)d_in[10];
    const float* ln_b   = (const float*)d_in[11];
    float* out = (float*)d_out;

    float *p_xz, *p_yg, *p_outp;
    cudaGetSymbolAddress((void**)&p_xz,   g_xz);
    cudaGetSymbolAddress((void**)&p_yg,   g_yg);
    cudaGetSymbolAddress((void**)&p_outp, g_outp);

    // 1) xz = x @ W_in   [2048,1024]@[1024,4096]
    {
        dim3 grid(XZW / 128, BL / 128);
        sgemm128<<<grid, 256>>>(x, W_in, p_xz, BL, XZW, DD);
    }
    // 2) conv + silu
    conv_silu_kernel<<<(BL * DIN) / 256, 256>>>(conv_w, conv_b);
    // 3) x_dbl = x_conv @ W_x
    {
        dim3 blk(96, 8);
        xdbl_kernel<<<BL / 8, blk>>>(W_x);
    }
    // 4) delta = softplus(dt @ W_dt + b_dt)
    delta_kernel<<<BL / 8, 256>>>(W_dt, b_dt);
    // 5) selective scan + gate
    scan_kernel<<<256, 256>>>(A_log, D_skip);
    // 6) out_pre = y_gated @ W_out   [2048,2048]@[2048,1024]
    {
        dim3 grid(DD / 128, BL / 128);
        sgemm128<<<grid, 256>>>(p_yg, W_out, p_outp, BL, DD, DIN);
    }
    // 7) LayerNorm
    ln_kernel<<<BL, 256>>>(ln_g, ln_b, out);
}

// round 5
// speedup vs baseline: 2.0966x; 2.0966x over previous
#include <cuda_runtime.h>
#include <cuda_bf16.h>
#include <math.h>
#include <stdint.h>

// Mamba dims
#define LL   1024
#define DD   1024
#define DIN  2048
#define NS   16
#define RR   64
#define BL   2048      // B*L
#define XZW  4096      // 2*DIN
#define XDW  128       // padded x_dbl width (96 -> 128)

// ---------------- scratch (device globals; no allocation allowed) ----------
__device__ float g_xz[BL * XZW];      // in_proj output [2048, 4096]
__device__ float g_xconv[BL * DIN];   // conv+silu     [2048, 2048]
__device__ float g_xdbl[BL * XDW];    // x_proj (padded) [2048, 128]
__device__ float g_delta[BL * DIN];   // raw dt@W_dt then softplus(+b) in place
__device__ float g_yg[BL * DIN];      // gated scan out [2048, 2048]
__device__ float g_outp[BL * DD];     // pre-LN output  [2048, 1024]

// bf16 split buffers: A (activations, [M,K]) and B^T (weights, [N,K])
__device__ __nv_bfloat16 g_ahi[4194304], g_alo[4194304];
__device__ __nv_bfloat16 g_bhi[4194304], g_blo[4194304];

// ============ warp-MMA bf16-split GEMM: C[M,N] = A@B^T (fp32 acc) ==========
// Block 256 thr = 8 warps (4M x 2N), block tile 128x128, warp tile 32x64.
// K-chunk 64 staged in smem with row stride 72 bf16 (36 words) -> conflict-free
// direct-LDS fragment loads per the m16n8k16 thread map.
#define KCH   64
#define TSTR  36                      // smem row stride in 32-bit words
#define TILEW (128 * TSTR)            // words per tile (4608) = 18432 B
#define WG_SMEM (4 * TILEW * 4)       // 4 tiles (Ah,Al,Bh,Bl) = 73728 B

__device__ __forceinline__ void mma_bf16(float* c, const uint32_t* a,
                                         uint32_t b0, uint32_t b1) {
    asm volatile(
        "mma.sync.aligned.m16n8k16.row.col.f32.bf16.bf16.f32 "
        "{%0,%1,%2,%3}, {%4,%5,%6,%7}, {%8,%9}, {%0,%1,%2,%3};"
        : "+f"(c[0]), "+f"(c[1]), "+f"(c[2]), "+f"(c[3])
        : "r"(a[0]), "r"(a[1]), "r"(a[2]), "r"(a[3]), "r"(b0), "r"(b1));
}

__global__ __launch_bounds__(256) void wgemm(float* __restrict__ C, int N, int K)
{
    extern __shared__ uint32_t sm[];
    uint32_t* sAh = sm;
    uint32_t* sAl = sm + TILEW;
    uint32_t* sBh = sm + 2 * TILEW;
    uint32_t* sBl = sm + 3 * TILEW;

    int tid  = threadIdx.x;
    int wid  = tid >> 5, lane = tid & 31;
    int wm   = wid >> 1, wn = wid & 1;       // 4 x 2 warp grid
    int m0   = blockIdx.y * 128, n0 = blockIdx.x * 128;
    int q    = lane >> 2, c4 = lane & 3;     // quad row / col-in-quad

    float acc[2][8][4];
    #pragma unroll
    for (int i = 0; i < 2; i++)
        #pragma unroll
        for (int j = 0; j < 8; j++)
            #pragma unroll
            for (int v = 0; v < 4; v++) acc[i][j][v] = 0.f;

    // loader mapping: 2 threads per row, each covers 32 contiguous bf16
    int lr = tid >> 1, lh = (tid & 1) * 32;
    uint32_t ldst = (uint32_t)lr * TSTR + (lh >> 1);

    int NC = K / KCH;
    for (int ch = 0; ch < NC; ch++) {
        size_t agoff = (size_t)(m0 + lr) * K + ch * KCH + lh;
        size_t bgoff = (size_t)(n0 + lr) * K + ch * KCH + lh;
        const uint4* pah = (const uint4*)(g_ahi + agoff);
        const uint4* pal = (const uint4*)(g_alo + agoff);
        const uint4* pbh = (const uint4*)(g_bhi + bgoff);
        const uint4* pbl = (const uint4*)(g_blo + bgoff);
        #pragma unroll
        for (int j = 0; j < 4; j++) {       // 4 x uint4 = 32 bf16
            *(uint4*)(sAh + ldst + j * 4) = pah[j];
            *(uint4*)(sAl + ldst + j * 4) = pal[j];
            *(uint4*)(sBh + ldst + j * 4) = pbh[j];
            *(uint4*)(sBl + ldst + j * 4) = pbl[j];
        }
        __syncthreads();

        #pragma unroll
        for (int ks = 0; ks < KCH / 16; ks++) {
            int cw = c4 + ks * 8;
            // A fragments (hi & lo) for 2 m-tiles
            uint32_t ah[2][4], al[2][4];
            #pragma unroll
            for (int mt = 0; mt < 2; mt++) {
                uint32_t base = (uint32_t)(wm * 32 + mt * 16 + q) * TSTR + cw;
                ah[mt][0] = sAh[base];
                ah[mt][1] = sAh[base + 8 * TSTR];
                ah[mt][2] = sAh[base + 4];
                ah[mt][3] = sAh[base + 8 * TSTR + 4];
                al[mt][0] = sAl[base];
                al[mt][1] = sAl[base + 8 * TSTR];
                al[mt][2] = sAl[base + 4];
                al[mt][3] = sAl[base + 8 * TSTR + 4];
            }
            #pragma unroll
            for (int nt = 0; nt < 8; nt++) {
                uint32_t nb = (uint32_t)(wn * 64 + nt * 8 + q) * TSTR + cw;
                uint32_t bh0 = sBh[nb], bh1 = sBh[nb + 4];
                uint32_t bl0 = sBl[nb], bl1 = sBl[nb + 4];
                #pragma unroll
                for (int mt = 0; mt < 2; mt++) {
                    mma_bf16(acc[mt][nt], ah[mt], bh0, bh1);
                    mma_bf16(acc[mt][nt], ah[mt], bl0, bl1);
                    mma_bf16(acc[mt][nt], al[mt], bh0, bh1);
                }
            }
        }
        __syncthreads();
    }

    // epilogue
    #pragma unroll
    for (int mt = 0; mt < 2; mt++) {
        int row = m0 + wm * 32 + mt * 16 + q;
        #pragma unroll
        for (int nt = 0; nt < 8; nt++) {
            int col = n0 + wn * 64 + nt * 8 + c4 * 2;
            *(float2*)(C + (size_t)row * N + col) =
                make_float2(acc[mt][nt][0], acc[mt][nt][1]);
            *(float2*)(C + (size_t)(row + 8) * N + col) =
                make_float2(acc[mt][nt][2], acc[mt][nt][3]);
        }
    }
}

// ---------- fp32 -> bf16 hi/lo split (strided src, contiguous dst) ---------
__global__ void cvt_split(const float* __restrict__ src, int cols, int ld, int total)
{
    int i = blockIdx.x * 256 + threadIdx.x;
    if (i >= total) return;
    int r = i / cols, c = i - r * cols;
    float a = src[(size_t)r * ld + c];
    __nv_bfloat16 h = __float2bfloat16(a);
    g_ahi[i] = h;
    g_alo[i] = __float2bfloat16(a - __bfloat162float(h));
}

// ---------- W [K,N] fp32 -> B^T [Nout,K] bf16 hi/lo (zero-pad n>=Nin) ------
__global__ void cvtT_split(const float* __restrict__ W, int Kd, int Nin)
{
    __shared__ float t[32][33];
    int k0 = blockIdx.x * 32, n0 = blockIdx.y * 32;
    int tx = threadIdx.x, ty = threadIdx.y;   // (32, 8)
    #pragma unroll
    for (int j = 0; j < 32; j += 8) {
        int n = n0 + tx;
        t[ty + j][tx] = (n < Nin) ? W[(size_t)(k0 + ty + j) * Nin + n] : 0.f;
    }
    __syncthreads();
    #pragma unroll
    for (int j = 0; j < 32; j += 8) {
        int n = n0 + ty + j, k = k0 + tx;
        float a = t[tx][ty + j];
        __nv_bfloat16 h = __float2bfloat16(a);
        size_t o = (size_t)n * Kd + k;
        g_bhi[o] = h;
        g_blo[o] = __float2bfloat16(a - __bfloat162float(h));
    }
}

// ---------------- causal depthwise conv (K=4) + SiLU ----------------------
__global__ void conv_silu_kernel(const float* __restrict__ conv_w,
                                 const float* __restrict__ conv_b)
{
    int idx = blockIdx.x * blockDim.x + threadIdx.x;   // over BL*DIN
    int d   = idx & (DIN - 1);
    int row = idx >> 11;
    int l   = row & (LL - 1);
    float acc = conv_b[d];
    #pragma unroll
    for (int k = 0; k < 4; k++) {
        int ll = l + k - 3;
        if (ll >= 0)
            acc = fmaf(g_xz[(size_t)(row + k - 3) * XZW + d], conv_w[d * 4 + k], acc);
    }
    acc = acc / (1.f + __expf(-acc));     // silu
    g_xconv[idx] = acc;
}

// ---------------- in-place: delta = softplus(delta_raw + b_dt) ------------
__global__ void softplus_bias(const float* __restrict__ b_dt)
{
    int i = blockIdx.x * 256 + threadIdx.x;
    float v = g_delta[i] + b_dt[i & (DIN - 1)];
    g_delta[i] = (v > 20.f) ? v : log1pf(__expf(v));
}

// ---------------- selective scan + D-skip + z-gate ------------------------
__global__ void scan_kernel(const float* __restrict__ A_log,
                            const float* __restrict__ D_skip)
{
    int lane = threadIdx.x & 31;
    int grp  = lane >> 4;
    int n    = lane & 15;
    int wglobal = blockIdx.x * (blockDim.x >> 5) + (threadIdx.x >> 5);
    int ch = wglobal * 2 + grp;    // 0..4095
    int b  = ch >> 11;
    int d  = ch & (DIN - 1);

    float a  = -__expf(A_log[d * NS + n]);
    float Dv = D_skip[d];

    const float* deltaP = g_delta + (size_t)(b * LL) * DIN + d;
    const float* xcP    = g_xconv + (size_t)(b * LL) * DIN + d;
    const float* zP     = g_xz    + (size_t)(b * LL) * XZW + DIN + d;
    const float* bcP    = g_xdbl  + (size_t)(b * LL) * XDW + RR + n;
    float*       ygP    = g_yg    + (size_t)(b * LL) * DIN + d;

    float h = 0.f;
    #pragma unroll 4
    for (int l = 0; l < LL; l++) {
        float dv = __ldg(deltaP + (size_t)l * DIN);
        float xv = __ldg(xcP + (size_t)l * DIN);
        float Bv = __ldg(bcP + (size_t)l * XDW);
        float Cv = __ldg(bcP + (size_t)l * XDW + NS);
        float dA = __expf(dv * a);
        h = fmaf(dA, h, dv * Bv * xv);
        float yc = h * Cv;
        yc += __shfl_xor_sync(0xFFFFFFFFu, yc, 8);
        yc += __shfl_xor_sync(0xFFFFFFFFu, yc, 4);
        yc += __shfl_xor_sync(0xFFFFFFFFu, yc, 2);
        yc += __shfl_xor_sync(0xFFFFFFFFu, yc, 1);
        if (n == 0) {
            float zv = zP[(size_t)l * XZW];
            float gate = zv / (1.f + __expf(-zv));
            ygP[(size_t)l * DIN] = (yc + xv * Dv) * gate;
        }
    }
}

// ---------------- LayerNorm (row = 1024) ----------------------------------
__global__ void ln_kernel(const float* __restrict__ lng,
                          const float* __restrict__ lnb,
                          float* __restrict__ out)
{
    int row = blockIdx.x, tid = threadIdx.x;
    float4 v = ((const float4*)(g_outp + (size_t)row * DD))[tid];
    float s  = v.x + v.y + v.z + v.w;
    float sq = fmaf(v.x, v.x, fmaf(v.y, v.y, fmaf(v.z, v.z, v.w * v.w)));
    #pragma unroll
    for (int o = 16; o > 0; o >>= 1) {
        s  += __shfl_xor_sync(0xFFFFFFFFu, s, o);
        sq += __shfl_xor_sync(0xFFFFFFFFu, sq, o);
    }
    __shared__ float ss[8], ssq[8];
    int w = tid >> 5, lane = tid & 31;
    if (!lane) { ss[w] = s; ssq[w] = sq; }
    __syncthreads();
    if (tid < 32) {
        s  = (lane < 8) ? ss[lane]  : 0.f;
        sq = (lane < 8) ? ssq[lane] : 0.f;
        #pragma unroll
        for (int o = 4; o > 0; o >>= 1) {
            s  += __shfl_xor_sync(0xFFFFFFFFu, s, o);
            sq += __shfl_xor_sync(0xFFFFFFFFu, sq, o);
        }
        if (!lane) { ss[0] = s; ssq[0] = sq; }
    }
    __syncthreads();
    float mu  = ss[0] * (1.f / 1024.f);
    float var = ssq[0] * (1.f / 1024.f) - mu * mu;
    float inv = rsqrtf(var + 1e-5f);
    float4 g4 = ((const float4*)lng)[tid];
    float4 b4 = ((const float4*)lnb)[tid];
    float4 o4;
    o4.x = (v.x - mu) * inv * g4.x + b4.x;
    o4.y = (v.y - mu) * inv * g4.y + b4.y;
    o4.z = (v.z - mu) * inv * g4.z + b4.z;
    o4.w = (v.w - mu) * inv * g4.w + b4.w;
    ((float4*)(out + (size_t)row * DD))[tid] = o4;
}

// ---------------- launcher -------------------------------------------------
extern "C" void kernel_launch(void* const* d_in, const int* in_sizes, int n_in,
                              void* d_out, int out_size)
{
    const float* x      = (const float*)d_in[0];
    const float* W_in   = (const float*)d_in[1];
    const float* conv_w = (const float*)d_in[2];
    const float* conv_b = (const float*)d_in[3];
    const float* W_x    = (const float*)d_in[4];
    const float* W_dt   = (const float*)d_in[5];
    const float* b_dt   = (const float*)d_in[6];
    const float* A_log  = (const float*)d_in[7];
    const float* D_skip = (const float*)d_in[8];
    const float* W_out  = (const float*)d_in[9];
    const float* ln_g   = (const float*)d_in[10];
    const float* ln_b   = (const float*)d_in[11];
    float* out = (float*)d_out;

    float *p_xz, *p_xconv, *p_xdbl, *p_delta, *p_yg, *p_outp;
    cudaGetSymbolAddress((void**)&p_xz,    g_xz);
    cudaGetSymbolAddress((void**)&p_xconv, g_xconv);
    cudaGetSymbolAddress((void**)&p_xdbl,  g_xdbl);
    cudaGetSymbolAddress((void**)&p_delta, g_delta);
    cudaGetSymbolAddress((void**)&p_yg,    g_yg);
    cudaGetSymbolAddress((void**)&p_outp,  g_outp);

    cudaFuncSetAttribute(wgemm, cudaFuncAttributeMaxDynamicSharedMemorySize, WG_SMEM);

    dim3 tblk(32, 8);

    // 1) xz = x @ W_in   [2048,1024]@[1024,4096]
    cvt_split<<<(BL * DD) / 256, 256>>>(x, DD, DD, BL * DD);
    cvtT_split<<<dim3(DD / 32, XZW / 32), tblk>>>(W_in, DD, XZW);
    wgemm<<<dim3(XZW / 128, BL / 128), 256, WG_SMEM>>>(p_xz, XZW, DD);

    // 2) conv + silu
    conv_silu_kernel<<<(BL * DIN) / 256, 256>>>(conv_w, conv_b);

    // 3) x_dbl = x_conv @ W_x  (N padded 96 -> 128)
    cvt_split<<<(BL * DIN) / 256, 256>>>(p_xconv, DIN, DIN, BL * DIN);
    cvtT_split<<<dim3(DIN / 32, XDW / 32), tblk>>>(W_x, DIN, 96);
    wgemm<<<dim3(XDW / 128, BL / 128), 256, WG_SMEM>>>(p_xdbl, XDW, DIN);

    // 4) delta_raw = dt @ W_dt (K=64), then softplus(+b_dt) in place
    cvt_split<<<(BL * RR) / 256, 256>>>(p_xdbl, RR, XDW, BL * RR);
    cvtT_split<<<dim3(RR / 32, DIN / 32), tblk>>>(W_dt, RR, DIN);
    wgemm<<<dim3(DIN / 128, BL / 128), 256, WG_SMEM>>>(p_delta, DIN, RR);
    softplus_bias<<<(BL * DIN) / 256, 256>>>(b_dt);

    // 5) selective scan + gate
    scan_kernel<<<256, 256>>>(A_log, D_skip);

    // 6) out_pre = y_gated @ W_out   [2048,2048]@[2048,1024]
    cvt_split<<<(BL * DIN) / 256, 256>>>(p_yg, DIN, DIN, BL * DIN);
    cvtT_split<<<dim3(DIN / 32, DD / 32), tblk>>>(W_out, DIN, DD);
    wgemm<<<dim3(DD / 128, BL / 128), 256, WG_SMEM>>>(p_outp, DD, DIN);

    // 7) LayerNorm
    ln_kernel<<<BL, 256>>>(ln_g, ln_b, out);
}

// round 6
// speedup vs baseline: 2.2251x; 1.0613x over previous
#include <cuda_runtime.h>
#include <cuda_bf16.h>
#include <math.h>
#include <stdint.h>

// Mamba dims
#define LL   1024
#define DD   1024
#define DIN  2048
#define NS   16
#define RR   64
#define BL   2048      // B*L
#define XZW  4096      // 2*DIN
#define XDW  128       // padded x_dbl width (96 -> 128)
#define KSPL 8         // split-K factor for GEMM2

// ---------------- scratch (device globals; no allocation allowed) ----------
__device__ float g_xz[BL * XZW];      // in_proj output [2048, 4096]
__device__ float g_xconv[BL * DIN];   // conv+silu     [2048, 2048]
__device__ float g_xdbl[BL * XDW];    // x_proj (padded) [2048, 128]
__device__ float g_delta[BL * DIN];   // softplus(dt@W_dt+b) [2048, 2048]
__device__ float g_outp[BL * DD];     // pre-LN output  [2048, 1024]
__device__ float g_part[KSPL * BL * XDW];  // split-K partials for GEMM2

// bf16 split buffers: A (activations, [M,K]) and B^T (weights, [N,K])
__device__ __nv_bfloat16 g_ahi[4194304], g_alo[4194304];
__device__ __nv_bfloat16 g_bhi[4194304], g_blo[4194304];

// ============ warp-MMA bf16-split GEMM: C[M,N] = A@B^T (fp32 acc) ==========
// Block 256 thr = 8 warps (4M x 2N), block tile 128x128, warp tile 32x64.
// K-chunk 32 in smem, stride 20 words (conflict-free), cp.async 2-stage pipe.
#define KCH   32
#define TSTR  20                      // smem row stride in 32-bit words
#define TILEW (128 * TSTR)            // 2560 words = 10240 B per tile
#define WG_SMEM (2 * 4 * TILEW * 4)   // 2 stages x 4 tiles = 81920 B

__device__ __forceinline__ uint32_t s2u(const void* p) {
    uint32_t a;
    asm("{ .reg .u64 t; cvta.to.shared.u64 t, %1; cvt.u32.u64 %0, t; }"
        : "=r"(a) : "l"(p));
    return a;
}
__device__ __forceinline__ void cpa16(uint32_t dst, const void* src) {
    asm volatile("cp.async.cg.shared.global [%0], [%1], 16;" :: "r"(dst), "l"(src));
}
__device__ __forceinline__ void cpa_commit() {
    asm volatile("cp.async.commit_group;" ::: "memory");
}
template <int N_>
__device__ __forceinline__ void cpa_wait() {
    asm volatile("cp.async.wait_group %0;" :: "n"(N_) : "memory");
}

__device__ __forceinline__ void mma_bf16(float* c, const uint32_t* a,
                                         uint32_t b0, uint32_t b1) {
    asm volatile(
        "mma.sync.aligned.m16n8k16.row.col.f32.bf16.bf16.f32 "
        "{%0,%1,%2,%3}, {%4,%5,%6,%7}, {%8,%9}, {%0,%1,%2,%3};"
        : "+f"(c[0]), "+f"(c[1]), "+f"(c[2]), "+f"(c[3])
        : "r"(a[0]), "r"(a[1]), "r"(a[2]), "r"(a[3]), "r"(b0), "r"(b1));
}

// mode 0: plain store; mode 1: softplus(v + bias[col]) store
__global__ __launch_bounds__(256) void wgemm(float* __restrict__ C, int N, int K,
                                             int kper, const float* __restrict__ bias,
                                             int mode)
{
    extern __shared__ uint32_t sm[];
    uint32_t smb = s2u(sm);

    int tid  = threadIdx.x;
    int wid  = tid >> 5, lane = tid & 31;
    int wm   = wid >> 1, wn = wid & 1;       // 4 x 2 warp grid
    int m0   = blockIdx.y * 128, n0 = blockIdx.x * 128;
    int q    = lane >> 2, c4 = lane & 3;
    int kbeg = blockIdx.z * kper;
    int NC   = kper / KCH;

    float acc[2][8][4];
    #pragma unroll
    for (int i = 0; i < 2; i++)
        #pragma unroll
        for (int j = 0; j < 8; j++)
            #pragma unroll
            for (int v = 0; v < 4; v++) acc[i][j][v] = 0.f;

    // loader mapping: 2 threads per row, each covers 16 contiguous bf16 (2x16B)
    int lr = tid >> 1;                 // row 0..127
    int lc = (tid & 1) * 16;           // bf16 offset in 32
    uint32_t sdw = (uint32_t)lr * TSTR + (tid & 1) * 8;  // word offset in tile

    size_t aoff0 = (size_t)(m0 + lr) * K + kbeg + lc;
    size_t boff0 = (size_t)(n0 + lr) * K + kbeg + lc;

    // issue chunk-load for chunk c into stage s
    auto load_chunk = [&](int c, int s) {
        int ko = c * KCH;
        const __nv_bfloat16* srcs[4] = {
            g_ahi + aoff0 + ko, g_alo + aoff0 + ko,
            g_bhi + boff0 + ko, g_blo + boff0 + ko };
        #pragma unroll
        for (int t = 0; t < 4; t++) {
            uint32_t dst = smb + (((uint32_t)(s * 4 + t)) * TILEW + sdw) * 4;
            cpa16(dst,      srcs[t]);
            cpa16(dst + 16, srcs[t] + 8);
        }
    };

    load_chunk(0, 0);
    cpa_commit();

    for (int ch = 0; ch < NC; ch++) {
        if (ch + 1 < NC) {
            load_chunk(ch + 1, (ch + 1) & 1);
            cpa_commit();
            cpa_wait<1>();
        } else {
            cpa_wait<0>();
        }
        __syncthreads();

        int s = ch & 1;
        const uint32_t* sAh = sm + (s * 4 + 0) * TILEW;
        const uint32_t* sAl = sm + (s * 4 + 1) * TILEW;
        const uint32_t* sBh = sm + (s * 4 + 2) * TILEW;
        const uint32_t* sBl = sm + (s * 4 + 3) * TILEW;

        #pragma unroll
        for (int ks = 0; ks < KCH / 16; ks++) {
            int cw = c4 + ks * 8;
            uint32_t ah[2][4], al[2][4];
            #pragma unroll
            for (int mt = 0; mt < 2; mt++) {
                uint32_t base = (uint32_t)(wm * 32 + mt * 16 + q) * TSTR + cw;
                ah[mt][0] = sAh[base];
                ah[mt][1] = sAh[base + 8 * TSTR];
                ah[mt][2] = sAh[base + 4];
                ah[mt][3] = sAh[base + 8 * TSTR + 4];
                al[mt][0] = sAl[base];
                al[mt][1] = sAl[base + 8 * TSTR];
                al[mt][2] = sAl[base + 4];
                al[mt][3] = sAl[base + 8 * TSTR + 4];
            }
            #pragma unroll
            for (int nt = 0; nt < 8; nt++) {
                uint32_t nb = (uint32_t)(wn * 64 + nt * 8 + q) * TSTR + cw;
                uint32_t bh0 = sBh[nb], bh1 = sBh[nb + 4];
                uint32_t bl0 = sBl[nb], bl1 = sBl[nb + 4];
                #pragma unroll
                for (int mt = 0; mt < 2; mt++) {
                    mma_bf16(acc[mt][nt], ah[mt], bh0, bh1);
                    mma_bf16(acc[mt][nt], ah[mt], bl0, bl1);
                    mma_bf16(acc[mt][nt], al[mt], bh0, bh1);
                }
            }
        }
        __syncthreads();
    }

    // epilogue (split-K slices write to disjoint partial planes)
    size_t zoff = (size_t)blockIdx.z * (size_t)(gridDim.y * 128) * N;
    #pragma unroll
    for (int mt = 0; mt < 2; mt++) {
        int row = m0 + wm * 32 + mt * 16 + q;
        #pragma unroll
        for (int nt = 0; nt < 8; nt++) {
            int col = n0 + wn * 64 + nt * 8 + c4 * 2;
            float v0 = acc[mt][nt][0], v1 = acc[mt][nt][1];
            float v2 = acc[mt][nt][2], v3 = acc[mt][nt][3];
            if (mode == 1) {
                float b0 = bias[col], b1 = bias[col + 1];
                v0 += b0; v1 += b1; v2 += b0; v3 += b1;
                v0 = (v0 > 20.f) ? v0 : log1pf(__expf(v0));
                v1 = (v1 > 20.f) ? v1 : log1pf(__expf(v1));
                v2 = (v2 > 20.f) ? v2 : log1pf(__expf(v2));
                v3 = (v3 > 20.f) ? v3 : log1pf(__expf(v3));
            }
            *(float2*)(C + zoff + (size_t)row * N + col)       = make_float2(v0, v1);
            *(float2*)(C + zoff + (size_t)(row + 8) * N + col) = make_float2(v2, v3);
        }
    }
}

// ---------------- reduce split-K partials into g_xdbl ----------------------
__global__ void reduce_part()
{
    int i = blockIdx.x * 256 + threadIdx.x;       // over BL*XDW
    float s = 0.f;
    #pragma unroll
    for (int z = 0; z < KSPL; z++) s += g_part[(size_t)z * (BL * XDW) + i];
    g_xdbl[i] = s;
}

// ---------- fp32 -> bf16 hi/lo split (strided src, contiguous dst) ---------
__global__ void cvt_split(const float* __restrict__ src, int cols, int ld, int total)
{
    int i = blockIdx.x * 256 + threadIdx.x;
    if (i >= total) return;
    int r = i / cols, c = i - r * cols;
    float a = src[(size_t)r * ld + c];
    __nv_bfloat16 h = __float2bfloat16(a);
    g_ahi[i] = h;
    g_alo[i] = __float2bfloat16(a - __bfloat162float(h));
}

// ---------- W [K,N] fp32 -> B^T [Nout,K] bf16 hi/lo (zero-pad n>=Nin) ------
__global__ void cvtT_split(const float* __restrict__ W, int Kd, int Nin)
{
    __shared__ float t[32][33];
    int k0 = blockIdx.x * 32, n0 = blockIdx.y * 32;
    int tx = threadIdx.x, ty = threadIdx.y;   // (32, 8)
    #pragma unroll
    for (int j = 0; j < 32; j += 8) {
        int n = n0 + tx;
        t[ty + j][tx] = (n < Nin) ? W[(size_t)(k0 + ty + j) * Nin + n] : 0.f;
    }
    __syncthreads();
    #pragma unroll
    for (int j = 0; j < 32; j += 8) {
        int n = n0 + ty + j, k = k0 + tx;
        float a = t[tx][ty + j];
        __nv_bfloat16 h = __float2bfloat16(a);
        size_t o = (size_t)n * Kd + k;
        g_bhi[o] = h;
        g_blo[o] = __float2bfloat16(a - __bfloat162float(h));
    }
}

// -------- causal depthwise conv (K=4) + SiLU; emits fp32 + bf16 split ------
__global__ void conv_silu_kernel(const float* __restrict__ conv_w,
                                 const float* __restrict__ conv_b)
{
    int idx = blockIdx.x * blockDim.x + threadIdx.x;   // over BL*DIN
    int d   = idx & (DIN - 1);
    int row = idx >> 11;
    int l   = row & (LL - 1);
    float acc = conv_b[d];
    #pragma unroll
    for (int k = 0; k < 4; k++) {
        int ll = l + k - 3;
        if (ll >= 0)
            acc = fmaf(g_xz[(size_t)(row + k - 3) * XZW + d], conv_w[d * 4 + k], acc);
    }
    acc = acc / (1.f + __expf(-acc));     // silu
    g_xconv[idx] = acc;
    __nv_bfloat16 h = __float2bfloat16(acc);
    g_ahi[idx] = h;
    g_alo[idx] = __float2bfloat16(acc - __bfloat162float(h));
}

// ---- selective scan + D-skip + z-gate; emits yg as bf16 split directly ----
__global__ void scan_kernel(const float* __restrict__ A_log,
                            const float* __restrict__ D_skip)
{
    int lane = threadIdx.x & 31;
    int grp  = lane >> 4;
    int n    = lane & 15;
    int wglobal = blockIdx.x * (blockDim.x >> 5) + (threadIdx.x >> 5);
    int ch = wglobal * 2 + grp;    // 0..4095
    int b  = ch >> 11;
    int d  = ch & (DIN - 1);

    float a  = -__expf(A_log[d * NS + n]);
    float Dv = D_skip[d];

    const float* deltaP = g_delta + (size_t)(b * LL) * DIN + d;
    const float* xcP    = g_xconv + (size_t)(b * LL) * DIN + d;
    const float* zP     = g_xz    + (size_t)(b * LL) * XZW + DIN + d;
    const float* bcP    = g_xdbl  + (size_t)(b * LL) * XDW + RR + n;
    size_t ygbase = (size_t)(b * LL) * DIN + d;

    float h = 0.f;
    #pragma unroll 4
    for (int l = 0; l < LL; l++) {
        float dv = __ldg(deltaP + (size_t)l * DIN);
        float xv = __ldg(xcP + (size_t)l * DIN);
        float Bv = __ldg(bcP + (size_t)l * XDW);
        float Cv = __ldg(bcP + (size_t)l * XDW + NS);
        float dA = __expf(dv * a);
        h = fmaf(dA, h, dv * Bv * xv);
        float yc = h * Cv;
        yc += __shfl_xor_sync(0xFFFFFFFFu, yc, 8);
        yc += __shfl_xor_sync(0xFFFFFFFFu, yc, 4);
        yc += __shfl_xor_sync(0xFFFFFFFFu, yc, 2);
        yc += __shfl_xor_sync(0xFFFFFFFFu, yc, 1);
        if (n == 0) {
            float zv = zP[(size_t)l * XZW];
            float gate = zv / (1.f + __expf(-zv));
            float val = (yc + xv * Dv) * gate;
            __nv_bfloat16 hh = __float2bfloat16(val);
            size_t o = ygbase + (size_t)l * DIN;
            g_ahi[o] = hh;
            g_alo[o] = __float2bfloat16(val - __bfloat162float(hh));
        }
    }
}

// ---------------- LayerNorm (row = 1024) ----------------------------------
__global__ void ln_kernel(const float* __restrict__ lng,
                          const float* __restrict__ lnb,
                          float* __restrict__ out)
{
    int row = blockIdx.x, tid = threadIdx.x;
    float4 v = ((const float4*)(g_outp + (size_t)row * DD))[tid];
    float s  = v.x + v.y + v.z + v.w;
    float sq = fmaf(v.x, v.x, fmaf(v.y, v.y, fmaf(v.z, v.z, v.w * v.w)));
    #pragma unroll
    for (int o = 16; o > 0; o >>= 1) {
        s  += __shfl_xor_sync(0xFFFFFFFFu, s, o);
        sq += __shfl_xor_sync(0xFFFFFFFFu, sq, o);
    }
    __shared__ float ss[8], ssq[8];
    int w = tid >> 5, lane = tid & 31;
    if (!lane) { ss[w] = s; ssq[w] = sq; }
    __syncthreads();
    if (tid < 32) {
        s  = (lane < 8) ? ss[lane]  : 0.f;
        sq = (lane < 8) ? ssq[lane] : 0.f;
        #pragma unroll
        for (int o = 4; o > 0; o >>= 1) {
            s  += __shfl_xor_sync(0xFFFFFFFFu, s, o);
            sq += __shfl_xor_sync(0xFFFFFFFFu, sq, o);
        }
        if (!lane) { ss[0] = s; ssq[0] = sq; }
    }
    __syncthreads();
    float mu  = ss[0] * (1.f / 1024.f);
    float var = ssq[0] * (1.f / 1024.f) - mu * mu;
    float inv = rsqrtf(var + 1e-5f);
    float4 g4 = ((const float4*)lng)[tid];
    float4 b4 = ((const float4*)lnb)[tid];
    float4 o4;
    o4.x = (v.x - mu) * inv * g4.x + b4.x;
    o4.y = (v.y - mu) * inv * g4.y + b4.y;
    o4.z = (v.z - mu) * inv * g4.z + b4.z;
    o4.w = (v.w - mu) * inv * g4.w + b4.w;
    ((float4*)(out + (size_t)row * DD))[tid] = o4;
}

// ---------------- launcher -------------------------------------------------
extern "C" void kernel_launch(void* const* d_in, const int* in_sizes, int n_in,
                              void* d_out, int out_size)
{
    const float* x      = (const float*)d_in[0];
    const float* W_in   = (const float*)d_in[1];
    const float* conv_w = (const float*)d_in[2];
    const float* conv_b = (const float*)d_in[3];
    const float* W_x    = (const float*)d_in[4];
    const float* W_dt   = (const float*)d_in[5];
    const float* b_dt   = (const float*)d_in[6];
    const float* A_log  = (const float*)d_in[7];
    const float* D_skip = (const float*)d_in[8];
    const float* W_out  = (const float*)d_in[9];
    const float* ln_g   = (const float*)d_in[10];
    const float* ln_b   = (const float*)d_in[11];
    float* out = (float*)d_out;

    float *p_xz, *p_xdbl, *p_delta, *p_outp, *p_part;
    cudaGetSymbolAddress((void**)&p_xz,    g_xz);
    cudaGetSymbolAddress((void**)&p_xdbl,  g_xdbl);
    cudaGetSymbolAddress((void**)&p_delta, g_delta);
    cudaGetSymbolAddress((void**)&p_outp,  g_outp);
    cudaGetSymbolAddress((void**)&p_part,  g_part);

    cudaFuncSetAttribute(wgemm, cudaFuncAttributeMaxDynamicSharedMemorySize, WG_SMEM);

    dim3 tblk(32, 8);

    // 1) xz = x @ W_in   [2048,1024]@[1024,4096]
    cvt_split<<<(BL * DD) / 256, 256>>>(x, DD, DD, BL * DD);
    cvtT_split<<<dim3(DD / 32, XZW / 32), tblk>>>(W_in, DD, XZW);
    wgemm<<<dim3(XZW / 128, BL / 128, 1), 256, WG_SMEM>>>(p_xz, XZW, DD, DD, nullptr, 0);

    // 2) conv + silu (emits fp32 + bf16 split for next GEMM)
    conv_silu_kernel<<<(BL * DIN) / 256, 256>>>(conv_w, conv_b);

    // 3) x_dbl = x_conv @ W_x  (N padded 96->128), 8-way split-K + reduce
    cvtT_split<<<dim3(DIN / 32, XDW / 32), tblk>>>(W_x, DIN, 96);
    wgemm<<<dim3(XDW / 128, BL / 128, KSPL), 256, WG_SMEM>>>(p_part, XDW, DIN,
                                                             DIN / KSPL, nullptr, 0);
    reduce_part<<<(BL * XDW) / 256, 256>>>();

    // 4) delta = softplus(dt @ W_dt + b_dt)   (bias+softplus fused in epilogue)
    cvt_split<<<(BL * RR) / 256, 256>>>(p_xdbl, RR, XDW, BL * RR);
    cvtT_split<<<dim3(RR / 32, DIN / 32), tblk>>>(W_dt, RR, DIN);
    wgemm<<<dim3(DIN / 128, BL / 128, 1), 256, WG_SMEM>>>(p_delta, DIN, RR, RR, b_dt, 1);

    // 5) selective scan + gate (emits yg bf16 split directly)
    scan_kernel<<<256, 256>>>(A_log, D_skip);

    // 6) out_pre = y_gated @ W_out   [2048,2048]@[2048,1024]
    cvtT_split<<<dim3(DIN / 32, DD / 32), tblk>>>(W_out, DIN, DD);
    wgemm<<<dim3(DD / 128, BL / 128, 1), 256, WG_SMEM>>>(p_outp, DD, DIN, DIN, nullptr, 0);

    // 7) LayerNorm
    ln_kernel<<<BL, 256>>>(ln_g, ln_b, out);
}

// round 7
// speedup vs baseline: 2.3229x; 1.0440x over previous
#include <cuda_runtime.h>
#include <cuda_fp16.h>
#include <math.h>
#include <stdint.h>

// Mamba dims
#define LL   1024
#define DD   1024
#define DIN  2048
#define NS   16
#define RR   64
#define BL   2048      // B*L
#define XZW  4096      // 2*DIN
#define XDW  128       // padded x_dbl width (96 -> 128)
#define KS2  16        // split-K factor for GEMM2
#define KS4  4         // split-K factor for GEMM4

// ---------------- scratch (device globals; no allocation allowed) ----------
__device__ float g_xz[BL * XZW];      // in_proj output [2048, 4096]
__device__ float g_xconv[BL * DIN];   // conv+silu     [2048, 2048]
__device__ float g_xdbl[BL * XDW];    // x_proj (padded) [2048, 128]
__device__ float g_delta[BL * DIN];   // softplus(dt@W_dt+b) [2048, 2048]
__device__ float g_outp[BL * DD];     // pre-LN output  [2048, 1024]
__device__ float g_part[8388608];     // split-K partials (max 4 x 2048 x 1024)

// fp16 split buffers: activations A hi/lo [M,K]; weights B^T hi-only [N,K]
__device__ __half g_ahi[4194304], g_alo[4194304];
__device__ __half g_w1[4194304];      // W_in^T  [4096,1024]
__device__ __half g_w2[262144];       // W_x^T   [128,2048] (pad 96->128)
__device__ __half g_w3[131072];       // W_dt^T  [2048,64]
__device__ __half g_w4[2097152];      // W_out^T [1024,2048]

// ============ warp-MMA fp16-split GEMM: C[M,N] = A@B^T (fp32 acc) ==========
// Block 256 thr = 8 warps (4M x 2N), block tile 128x128, warp tile 32x64.
// K-chunk 32 in smem, stride 20 words (conflict-free), cp.async 2-stage pipe.
// Products: ah*bh + al*bh  (B residual dropped; rel err ~2^-12)
#define KCH   32
#define TSTR  20                      // smem row stride in 32-bit words
#define TILEW (128 * TSTR)            // 2560 words = 10240 B per tile
#define WG_SMEM (2 * 3 * TILEW * 4)   // 2 stages x 3 tiles = 61440 B

__device__ __forceinline__ uint32_t s2u(const void* p) {
    uint32_t a;
    asm("{ .reg .u64 t; cvta.to.shared.u64 t, %1; cvt.u32.u64 %0, t; }"
        : "=r"(a) : "l"(p));
    return a;
}
__device__ __forceinline__ void cpa16(uint32_t dst, const void* src) {
    asm volatile("cp.async.cg.shared.global [%0], [%1], 16;" :: "r"(dst), "l"(src));
}
__device__ __forceinline__ void cpa_commit() {
    asm volatile("cp.async.commit_group;" ::: "memory");
}
template <int N_>
__device__ __forceinline__ void cpa_wait() {
    asm volatile("cp.async.wait_group %0;" :: "n"(N_) : "memory");
}

__device__ __forceinline__ void mma_f16(float* c, const uint32_t* a,
                                        uint32_t b0, uint32_t b1) {
    asm volatile(
        "mma.sync.aligned.m16n8k16.row.col.f32.f16.f16.f32 "
        "{%0,%1,%2,%3}, {%4,%5,%6,%7}, {%8,%9}, {%0,%1,%2,%3};"
        : "+f"(c[0]), "+f"(c[1]), "+f"(c[2]), "+f"(c[3])
        : "r"(a[0]), "r"(a[1]), "r"(a[2]), "r"(a[3]), "r"(b0), "r"(b1));
}

// mode 0: plain store; mode 1: softplus(v + bias[col]) store
__global__ __launch_bounds__(256) void wgemm(const __half* __restrict__ Bh,
                                             float* __restrict__ C, int N, int K,
                                             int kper, const float* __restrict__ bias,
                                             int mode)
{
    extern __shared__ uint32_t sm[];
    uint32_t smb = s2u(sm);

    int tid  = threadIdx.x;
    int wid  = tid >> 5, lane = tid & 31;
    int wm   = wid >> 1, wn = wid & 1;       // 4 x 2 warp grid
    int m0   = blockIdx.y * 128, n0 = blockIdx.x * 128;
    int q    = lane >> 2, c4 = lane & 3;
    int kbeg = blockIdx.z * kper;
    int NC   = kper / KCH;

    float acc[2][8][4];
    #pragma unroll
    for (int i = 0; i < 2; i++)
        #pragma unroll
        for (int j = 0; j < 8; j++)
            #pragma unroll
            for (int v = 0; v < 4; v++) acc[i][j][v] = 0.f;

    // loader mapping: 2 threads per row, each covers 16 contiguous fp16 (2x16B)
    int lr = tid >> 1;                 // row 0..127
    int lc = (tid & 1) * 16;           // fp16 offset in 32
    uint32_t sdw = (uint32_t)lr * TSTR + (tid & 1) * 8;  // word offset in tile

    size_t aoff0 = (size_t)(m0 + lr) * K + kbeg + lc;
    size_t boff0 = (size_t)(n0 + lr) * K + kbeg + lc;

    auto load_chunk = [&](int c, int s) {
        int ko = c * KCH;
        const __half* srcs[3] = { g_ahi + aoff0 + ko, g_alo + aoff0 + ko,
                                  Bh + boff0 + ko };
        #pragma unroll
        for (int t = 0; t < 3; t++) {
            uint32_t dst = smb + (((uint32_t)(s * 3 + t)) * TILEW + sdw) * 4;
            cpa16(dst,      srcs[t]);
            cpa16(dst + 16, srcs[t] + 8);
        }
    };

    load_chunk(0, 0);
    cpa_commit();

    for (int ch = 0; ch < NC; ch++) {
        if (ch + 1 < NC) {
            load_chunk(ch + 1, (ch + 1) & 1);
            cpa_commit();
            cpa_wait<1>();
        } else {
            cpa_wait<0>();
        }
        __syncthreads();

        int s = ch & 1;
        const uint32_t* sAh = sm + (s * 3 + 0) * TILEW;
        const uint32_t* sAl = sm + (s * 3 + 1) * TILEW;
        const uint32_t* sBh = sm + (s * 3 + 2) * TILEW;

        #pragma unroll
        for (int ks = 0; ks < KCH / 16; ks++) {
            int cw = c4 + ks * 8;
            uint32_t ah[2][4], al[2][4];
            #pragma unroll
            for (int mt = 0; mt < 2; mt++) {
                uint32_t base = (uint32_t)(wm * 32 + mt * 16 + q) * TSTR + cw;
                ah[mt][0] = sAh[base];
                ah[mt][1] = sAh[base + 8 * TSTR];
                ah[mt][2] = sAh[base + 4];
                ah[mt][3] = sAh[base + 8 * TSTR + 4];
                al[mt][0] = sAl[base];
                al[mt][1] = sAl[base + 8 * TSTR];
                al[mt][2] = sAl[base + 4];
                al[mt][3] = sAl[base + 8 * TSTR + 4];
            }
            #pragma unroll
            for (int nt = 0; nt < 8; nt++) {
                uint32_t nb = (uint32_t)(wn * 64 + nt * 8 + q) * TSTR + cw;
                uint32_t bh0 = sBh[nb], bh1 = sBh[nb + 4];
                #pragma unroll
                for (int mt = 0; mt < 2; mt++) {
                    mma_f16(acc[mt][nt], ah[mt], bh0, bh1);
                    mma_f16(acc[mt][nt], al[mt], bh0, bh1);
                }
            }
        }
        __syncthreads();
    }

    // epilogue (split-K slices write to disjoint partial planes)
    size_t zoff = (size_t)blockIdx.z * (size_t)(gridDim.y * 128) * N;
    #pragma unroll
    for (int mt = 0; mt < 2; mt++) {
        int row = m0 + wm * 32 + mt * 16 + q;
        #pragma unroll
        for (int nt = 0; nt < 8; nt++) {
            int col = n0 + wn * 64 + nt * 8 + c4 * 2;
            float v0 = acc[mt][nt][0], v1 = acc[mt][nt][1];
            float v2 = acc[mt][nt][2], v3 = acc[mt][nt][3];
            if (mode == 1) {
                float b0 = bias[col], b1 = bias[col + 1];
                v0 += b0; v1 += b1; v2 += b0; v3 += b1;
                v0 = (v0 > 20.f) ? v0 : log1pf(__expf(v0));
                v1 = (v1 > 20.f) ? v1 : log1pf(__expf(v1));
                v2 = (v2 > 20.f) ? v2 : log1pf(__expf(v2));
                v3 = (v3 > 20.f) ? v3 : log1pf(__expf(v3));
            }
            *(float2*)(C + zoff + (size_t)row * N + col)       = make_float2(v0, v1);
            *(float2*)(C + zoff + (size_t)(row + 8) * N + col) = make_float2(v2, v3);
        }
    }
}

// ---------------- reduce split-K partials -----------------------------------
__global__ void reduce_part2()      // 16 planes of BL*XDW -> g_xdbl
{
    int i = blockIdx.x * 256 + threadIdx.x;
    float s = 0.f;
    #pragma unroll
    for (int z = 0; z < KS2; z++) s += g_part[(size_t)z * (BL * XDW) + i];
    g_xdbl[i] = s;
}
__global__ void reduce_part4()      // 4 planes of BL*DD -> g_outp
{
    int i = blockIdx.x * 256 + threadIdx.x;
    float s = 0.f;
    #pragma unroll
    for (int z = 0; z < KS4; z++) s += g_part[(size_t)z * (BL * DD) + i];
    g_outp[i] = s;
}

// ---------- fp32 -> fp16 hi/lo split (strided src, contiguous dst) ---------
__global__ void cvt_split(const float* __restrict__ src, int cols, int ld, int total)
{
    int i = blockIdx.x * 256 + threadIdx.x;
    if (i >= total) return;
    int r = i / cols, c = i - r * cols;
    float a = src[(size_t)r * ld + c];
    __half h = __float2half(a);
    g_ahi[i] = h;
    g_alo[i] = __float2half(a - __half2float(h));
}

// ---------- W [K,N] fp32 -> B^T [Nout,K] fp16 hi-only (zero-pad) -----------
__global__ void cvtT_h(const float* __restrict__ W, __half* __restrict__ outw,
                       int Kd, int Nin)
{
    __shared__ float t[32][33];
    int k0 = blockIdx.x * 32, n0 = blockIdx.y * 32;
    int tx = threadIdx.x, ty = threadIdx.y;   // (32, 8)
    #pragma unroll
    for (int j = 0; j < 32; j += 8) {
        int n = n0 + tx;
        t[ty + j][tx] = (n < Nin) ? W[(size_t)(k0 + ty + j) * Nin + n] : 0.f;
    }
    __syncthreads();
    #pragma unroll
    for (int j = 0; j < 32; j += 8) {
        int n = n0 + ty + j, k = k0 + tx;
        outw[(size_t)n * Kd + k] = __float2half(t[tx][ty + j]);
    }
}

// -------- causal depthwise conv (K=4) + SiLU; emits fp32 + fp16 split ------
__global__ void conv_silu_kernel(const float* __restrict__ conv_w,
                                 const float* __restrict__ conv_b)
{
    int idx = blockIdx.x * blockDim.x + threadIdx.x;   // over BL*DIN
    int d   = idx & (DIN - 1);
    int row = idx >> 11;
    int l   = row & (LL - 1);
    float acc = conv_b[d];
    #pragma unroll
    for (int k = 0; k < 4; k++) {
        int ll = l + k - 3;
        if (ll >= 0)
            acc = fmaf(g_xz[(size_t)(row + k - 3) * XZW + d], conv_w[d * 4 + k], acc);
    }
    acc = acc / (1.f + __expf(-acc));     // silu
    g_xconv[idx] = acc;
    __half h = __float2half(acc);
    g_ahi[idx] = h;
    g_alo[idx] = __float2half(acc - __half2float(h));
}

// ---- selective scan + D-skip + z-gate; emits yg as fp16 split directly ----
__global__ void scan_kernel(const float* __restrict__ A_log,
                            const float* __restrict__ D_skip)
{
    int lane = threadIdx.x & 31;
    int grp  = lane >> 4;
    int n    = lane & 15;
    int wglobal = blockIdx.x * (blockDim.x >> 5) + (threadIdx.x >> 5);
    int ch = wglobal * 2 + grp;    // 0..4095
    int b  = ch >> 11;
    int d  = ch & (DIN - 1);

    float a  = -__expf(A_log[d * NS + n]);
    float Dv = D_skip[d];

    const float* deltaP = g_delta + (size_t)(b * LL) * DIN + d;
    const float* xcP    = g_xconv + (size_t)(b * LL) * DIN + d;
    const float* zP     = g_xz    + (size_t)(b * LL) * XZW + DIN + d;
    const float* bcP    = g_xdbl  + (size_t)(b * LL) * XDW + RR + n;
    size_t ygbase = (size_t)(b * LL) * DIN + d;

    float h = 0.f;
    #pragma unroll 4
    for (int l = 0; l < LL; l++) {
        float dv = __ldg(deltaP + (size_t)l * DIN);
        float xv = __ldg(xcP + (size_t)l * DIN);
        float Bv = __ldg(bcP + (size_t)l * XDW);
        float Cv = __ldg(bcP + (size_t)l * XDW + NS);
        float dA = __expf(dv * a);
        h = fmaf(dA, h, dv * Bv * xv);
        float yc = h * Cv;
        yc += __shfl_xor_sync(0xFFFFFFFFu, yc, 8);
        yc += __shfl_xor_sync(0xFFFFFFFFu, yc, 4);
        yc += __shfl_xor_sync(0xFFFFFFFFu, yc, 2);
        yc += __shfl_xor_sync(0xFFFFFFFFu, yc, 1);
        if (n == 0) {
            float zv = zP[(size_t)l * XZW];
            float gate = zv / (1.f + __expf(-zv));
            float val = (yc + xv * Dv) * gate;
            __half hh = __float2half(val);
            size_t o = ygbase + (size_t)l * DIN;
            g_ahi[o] = hh;
            g_alo[o] = __float2half(val - __half2float(hh));
        }
    }
}

// ---------------- LayerNorm (row = 1024) ----------------------------------
__global__ void ln_kernel(const float* __restrict__ lng,
                          const float* __restrict__ lnb,
                          float* __restrict__ out)
{
    int row = blockIdx.x, tid = threadIdx.x;
    float4 v = ((const float4*)(g_outp + (size_t)row * DD))[tid];
    float s  = v.x + v.y + v.z + v.w;
    float sq = fmaf(v.x, v.x, fmaf(v.y, v.y, fmaf(v.z, v.z, v.w * v.w)));
    #pragma unroll
    for (int o = 16; o > 0; o >>= 1) {
        s  += __shfl_xor_sync(0xFFFFFFFFu, s, o);
        sq += __shfl_xor_sync(0xFFFFFFFFu, sq, o);
    }
    __shared__ float ss[8], ssq[8];
    int w = tid >> 5, lane = tid & 31;
    if (!lane) { ss[w] = s; ssq[w] = sq; }
    __syncthreads();
    if (tid < 32) {
        s  = (lane < 8) ? ss[lane]  : 0.f;
        sq = (lane < 8) ? ssq[lane] : 0.f;
        #pragma unroll
        for (int o = 4; o > 0; o >>= 1) {
            s  += __shfl_xor_sync(0xFFFFFFFFu, s, o);
            sq += __shfl_xor_sync(0xFFFFFFFFu, sq, o);
        }
        if (!lane) { ss[0] = s; ssq[0] = sq; }
    }
    __syncthreads();
    float mu  = ss[0] * (1.f / 1024.f);
    float var = ssq[0] * (1.f / 1024.f) - mu * mu;
    float inv = rsqrtf(var + 1e-5f);
    float4 g4 = ((const float4*)lng)[tid];
    float4 b4 = ((const float4*)lnb)[tid];
    float4 o4;
    o4.x = (v.x - mu) * inv * g4.x + b4.x;
    o4.y = (v.y - mu) * inv * g4.y + b4.y;
    o4.z = (v.z - mu) * inv * g4.z + b4.z;
    o4.w = (v.w - mu) * inv * g4.w + b4.w;
    ((float4*)(out + (size_t)row * DD))[tid] = o4;
}

// ---------------- launcher -------------------------------------------------
extern "C" void kernel_launch(void* const* d_in, const int* in_sizes, int n_in,
                              void* d_out, int out_size)
{
    const float* x      = (const float*)d_in[0];
    const float* W_in   = (const float*)d_in[1];
    const float* conv_w = (const float*)d_in[2];
    const float* conv_b = (const float*)d_in[3];
    const float* W_x    = (const float*)d_in[4];
    const float* W_dt   = (const float*)d_in[5];
    const float* b_dt   = (const float*)d_in[6];
    const float* A_log  = (const float*)d_in[7];
    const float* D_skip = (const float*)d_in[8];
    const float* W_out  = (const float*)d_in[9];
    const float* ln_g   = (const float*)d_in[10];
    const float* ln_b   = (const float*)d_in[11];
    float* out = (float*)d_out;

    float *p_xz, *p_xdbl, *p_delta, *p_outp, *p_part;
    __half *p_w1, *p_w2, *p_w3, *p_w4;
    cudaGetSymbolAddress((void**)&p_xz,    g_xz);
    cudaGetSymbolAddress((void**)&p_xdbl,  g_xdbl);
    cudaGetSymbolAddress((void**)&p_delta, g_delta);
    cudaGetSymbolAddress((void**)&p_outp,  g_outp);
    cudaGetSymbolAddress((void**)&p_part,  g_part);
    cudaGetSymbolAddress((void**)&p_w1,    g_w1);
    cudaGetSymbolAddress((void**)&p_w2,    g_w2);
    cudaGetSymbolAddress((void**)&p_w3,    g_w3);
    cudaGetSymbolAddress((void**)&p_w4,    g_w4);

    cudaFuncSetAttribute(wgemm, cudaFuncAttributeMaxDynamicSharedMemorySize, WG_SMEM);

    dim3 tblk(32, 8);

    // 1) xz = x @ W_in   [2048,1024]@[1024,4096]
    cvt_split<<<(BL * DD) / 256, 256>>>(x, DD, DD, BL * DD);
    cvtT_h<<<dim3(DD / 32, XZW / 32), tblk>>>(W_in, p_w1, DD, XZW);
    wgemm<<<dim3(XZW / 128, BL / 128, 1), 256, WG_SMEM>>>(p_w1, p_xz, XZW, DD, DD,
                                                          nullptr, 0);

    // 2) conv + silu (emits fp32 + fp16 split for next GEMM)
    conv_silu_kernel<<<(BL * DIN) / 256, 256>>>(conv_w, conv_b);

    // 3) x_dbl = x_conv @ W_x  (N padded 96->128), 16-way split-K + reduce
    cvtT_h<<<dim3(DIN / 32, XDW / 32), tblk>>>(W_x, p_w2, DIN, 96);
    wgemm<<<dim3(XDW / 128, BL / 128, KS2), 256, WG_SMEM>>>(p_w2, p_part, XDW, DIN,
                                                            DIN / KS2, nullptr, 0);
    reduce_part2<<<(BL * XDW) / 256, 256>>>();

    // 4) delta = softplus(dt @ W_dt + b_dt)   (bias+softplus fused in epilogue)
    cvt_split<<<(BL * RR) / 256, 256>>>(p_xdbl, RR, XDW, BL * RR);
    cvtT_h<<<dim3(RR / 32, DIN / 32), tblk>>>(W_dt, p_w3, RR, DIN);
    wgemm<<<dim3(DIN / 128, BL / 128, 1), 256, WG_SMEM>>>(p_w3, p_delta, DIN, RR, RR,
                                                          b_dt, 1);

    // 5) selective scan + gate (emits yg fp16 split directly)
    scan_kernel<<<256, 256>>>(A_log, D_skip);

    // 6) out_pre = y_gated @ W_out   [2048,2048]@[2048,1024], 4-way split-K
    cvtT_h<<<dim3(DIN / 32, DD / 32), tblk>>>(W_out, p_w4, DIN, DD);
    wgemm<<<dim3(DD / 128, BL / 128, KS4), 256, WG_SMEM>>>(p_w4, p_part, DD, DIN,
                                                           DIN / KS4, nullptr, 0);
    reduce_part4<<<(BL * DD) / 256, 256>>>();

    // 7) LayerNorm
    ln_kernel<<<BL, 256>>>(ln_g, ln_b, out);
}